// round 3
// baseline (speedup 1.0000x reference)
#include <cuda_runtime.h>
#include <cuda_bf16.h>
#include <cstdint>

// ---------------- problem shape ----------------
static constexpr int B_ROWS = 16384;
static constexpr int C_ROWS = 4096;
static constexpr int KDIM   = 1024;

// ---------------- GEMM tiling (int8) ----------------
static constexpr int BM = 128;
static constexpr int BN = 128;
static constexpr int BK = 128;                // int8 elems (=bytes) per K-chunk
static constexpr int STAGES = 3;
static constexpr int KTILES = KDIM / BK;      // 8
static constexpr int KSTEPS = BK / 32;        // 4 imma k-steps (k32) per chunk

// padded smem rows: 128 + 16 bytes -> 144B stride (conflict-free ldmatrix)
static constexpr int ROW_B   = BK + 16;       // 144 bytes
static constexpr int TILE_B  = 128 * ROW_B;   // 18432 bytes per (A or B) stage
static constexpr int OFF_B0  = STAGES * TILE_B;
static constexpr int SMEM_BYTES = 2 * STAGES * TILE_B;  // 110592

// ---------------- device scratch (no cudaMalloc allowed) ----------------
__device__ uint8_t g_featq[(size_t)B_ROWS * KDIM];
__device__ uint8_t g_centq[(size_t)C_ROWS * KDIM];
__device__ float g_x2[B_ROWS];
__device__ float g_c2[C_ROWS];
__device__ float g_sx[B_ROWS];
__device__ float g_sc[C_ROWS];

// ---------------- PTX helpers ----------------
__device__ __forceinline__ uint32_t smem_u32(const void* p) {
    uint32_t a;
    asm("{ .reg .u64 t; cvta.to.shared.u64 t, %1; cvt.u32.u64 %0, t; }"
        : "=r"(a) : "l"(p));
    return a;
}

__device__ __forceinline__ void cp_async16(uint32_t s_addr, const void* g_addr) {
    asm volatile("cp.async.cg.shared.global [%0], [%1], 16;"
                 :: "r"(s_addr), "l"(g_addr) : "memory");
}
__device__ __forceinline__ void cp_commit() {
    asm volatile("cp.async.commit_group;" ::: "memory");
}
template <int N>
__device__ __forceinline__ void cp_wait() {
    asm volatile("cp.async.wait_group %0;" :: "n"(N) : "memory");
}

__device__ __forceinline__ void ldsm_x4(uint32_t& r0, uint32_t& r1, uint32_t& r2, uint32_t& r3,
                                        uint32_t addr) {
    asm volatile("ldmatrix.sync.aligned.m8n8.x4.shared.b16 {%0,%1,%2,%3}, [%4];"
                 : "=r"(r0), "=r"(r1), "=r"(r2), "=r"(r3) : "r"(addr));
}

// int8 IMMA m16n8k32, s32 accumulate
__device__ __forceinline__ void imma16832(int* d, uint32_t a0, uint32_t a1, uint32_t a2,
                                          uint32_t a3, uint32_t b0, uint32_t b1) {
    asm volatile(
        "mma.sync.aligned.m16n8k32.row.col.s32.s8.s8.s32 "
        "{%0,%1,%2,%3}, {%4,%5,%6,%7}, {%8,%9}, {%0,%1,%2,%3};"
        : "+r"(d[0]), "+r"(d[1]), "+r"(d[2]), "+r"(d[3])
        : "r"(a0), "r"(a1), "r"(a2), "r"(a3), "r"(b0), "r"(b1));
}

// ---------------- prep: fp32 -> int8 (per-row symmetric) + row sum-of-squares ----------------
__global__ __launch_bounds__(256)
void prep_kernel(const float* __restrict__ in, uint8_t* __restrict__ outq,
                 float* __restrict__ sq, float* __restrict__ scale) {
    int row = blockIdx.x;
    int t = threadIdx.x;
    float4 v = reinterpret_cast<const float4*>(in)[(size_t)row * 256 + t];

    float s = fmaf(v.x, v.x, fmaf(v.y, v.y, fmaf(v.z, v.z, v.w * v.w)));
    float m = fmaxf(fmaxf(fabsf(v.x), fabsf(v.y)), fmaxf(fabsf(v.z), fabsf(v.w)));
    #pragma unroll
    for (int o = 16; o > 0; o >>= 1) {
        s += __shfl_xor_sync(0xFFFFFFFFu, s, o);
        m = fmaxf(m, __shfl_xor_sync(0xFFFFFFFFu, m, o));
    }
    __shared__ float ws[8], wm[8];
    __shared__ float fin_s, fin_m;
    if ((t & 31) == 0) { ws[t >> 5] = s; wm[t >> 5] = m; }
    __syncthreads();
    if (t < 8) {
        float x = ws[t], y = wm[t];
        #pragma unroll
        for (int o = 4; o > 0; o >>= 1) {
            x += __shfl_xor_sync(0xFFu, x, o);
            y = fmaxf(y, __shfl_xor_sync(0xFFu, y, o));
        }
        if (t == 0) {
            fin_s = x;
            fin_m = (y > 0.0f) ? y : 1.0f;
            sq[row] = x;
            scale[row] = fin_m * (1.0f / 127.0f);
        }
    }
    __syncthreads();

    float inv = 127.0f / fin_m;
    int q0 = max(-127, min(127, __float2int_rn(v.x * inv)));
    int q1 = max(-127, min(127, __float2int_rn(v.y * inv)));
    int q2 = max(-127, min(127, __float2int_rn(v.z * inv)));
    int q3 = max(-127, min(127, __float2int_rn(v.w * inv)));
    uint32_t packed = (uint32_t)(q0 & 0xFF) | ((uint32_t)(q1 & 0xFF) << 8) |
                      ((uint32_t)(q2 & 0xFF) << 16) | ((uint32_t)(q3 & 0xFF) << 24);
    reinterpret_cast<uint32_t*>(outq)[(size_t)row * 256 + t] = packed;
}

// ---------------- main int8 GEMM + fused distance epilogue ----------------
__global__ __launch_bounds__(256, 2)
void dist_gemm_kernel(const uint8_t* __restrict__ Aq,
                      const uint8_t* __restrict__ Bq,
                      const float* __restrict__ x2,
                      const float* __restrict__ c2,
                      const float* __restrict__ sx,
                      const float* __restrict__ sc,
                      float* __restrict__ out) {
    extern __shared__ char smem[];
    const uint32_t sb = smem_u32(smem);
    const int tid = threadIdx.x;
    const int wid = tid >> 5;
    const int lane = tid & 31;

    // n-fast tile mapping for L2 reuse of the A (feat) tile across a wave
    const int nt = blockIdx.x & 31;           // 32 n-tiles
    const int mt = blockIdx.x >> 5;           // 128 m-tiles
    const int m_base = mt * BM;
    const int n_base = nt * BN;

    // cp.async: 8 x 16B chunks per 128B row; 1024 chunks per stage; 4/thread
    auto load_stage = [&](int s, int kt) {
        const uint32_t sA = sb + s * TILE_B;
        const uint32_t sB = sb + OFF_B0 + s * TILE_B;
        const uint8_t* gA = Aq + (size_t)m_base * KDIM + kt * BK;
        const uint8_t* gB = Bq + (size_t)n_base * KDIM + kt * BK;
        #pragma unroll
        for (int i = 0; i < 4; i++) {
            int cid = tid + i * 256;
            int row = cid >> 3, c = cid & 7;
            cp_async16(sA + row * ROW_B + c * 16, gA + (size_t)row * KDIM + c * 16);
        }
        #pragma unroll
        for (int i = 0; i < 4; i++) {
            int cid = tid + i * 256;
            int row = cid >> 3, c = cid & 7;
            cp_async16(sB + row * ROW_B + c * 16, gB + (size_t)row * KDIM + c * 16);
        }
    };

    // warp tiling: 2 (M) x 4 (N); each warp 64x32
    const int wm = wid >> 2;                  // 0..1
    const int wn = wid & 3;                   // 0..3

    int acc[4][4][4];                         // [mtile][ntile][frag]
    #pragma unroll
    for (int i = 0; i < 4; i++)
        #pragma unroll
        for (int j = 0; j < 4; j++)
            #pragma unroll
            for (int f = 0; f < 4; f++) acc[i][j][f] = 0;

    // ldmatrix lane address components (byte units)
    const int a_row_l = (lane & 15);             // rows 0-15 within 16-row group
    const int a_koff  = (lane >> 4) * 16;        // k-byte group 0 / 16
    const int b_koff  = ((lane >> 3) & 1) * 16;  // k-byte group 0 / 16

    // prologue: fill 3 stages
    load_stage(0, 0); cp_commit();
    load_stage(1, 1); cp_commit();
    load_stage(2, 2); cp_commit();

    #pragma unroll 1
    for (int kt = 0; kt < KTILES; kt++) {
        const int s = kt % STAGES;
        cp_wait<2>();
        __syncthreads();

        const uint32_t sA = sb + s * TILE_B;
        const uint32_t sB = sb + OFF_B0 + s * TILE_B;

        #pragma unroll
        for (int kk = 0; kk < KSTEPS; kk++) {
            const int k0 = kk * 32;              // 32 int8 per k-step
            // A frags (4 mtiles of 16 rows)
            uint32_t af[4][4];
            #pragma unroll
            for (int i = 0; i < 4; i++) {
                int row = wm * 64 + i * 16 + a_row_l;
                uint32_t addr = sA + row * ROW_B + k0 + a_koff;
                ldsm_x4(af[i][0], af[i][1], af[i][2], af[i][3], addr);
            }
            // B frags (4 ntiles via 2 x4-ldmatrix)
            uint32_t bf[4][2];
            #pragma unroll
            for (int j = 0; j < 2; j++) {
                int n = wn * 32 + (2 * j + (lane >> 4)) * 8 + (lane & 7);
                uint32_t addr = sB + n * ROW_B + k0 + b_koff;
                uint32_t r0, r1, r2, r3;
                ldsm_x4(r0, r1, r2, r3, addr);
                bf[2 * j][0] = r0; bf[2 * j][1] = r1;
                bf[2 * j + 1][0] = r2; bf[2 * j + 1][1] = r3;
            }
            // 16 IMMA
            #pragma unroll
            for (int i = 0; i < 4; i++)
                #pragma unroll
                for (int j = 0; j < 4; j++)
                    imma16832(acc[i][j], af[i][0], af[i][1], af[i][2], af[i][3],
                              bf[j][0], bf[j][1]);
        }

        __syncthreads();
        if (kt + STAGES < KTILES) load_stage(s, kt + STAGES);
        cp_commit();
    }

    // ---------------- epilogue: dist = x2[m] + c2[n] - 2*sx*sc*acc ----------------
    const int g = lane >> 2;          // row group 0..7
    const int q = lane & 3;           // col quad
    #pragma unroll
    for (int i = 0; i < 4; i++) {
        const int r0 = m_base + wm * 64 + i * 16 + g;
        const int r1 = r0 + 8;
        const float x0 = __ldg(&x2[r0]);
        const float x1 = __ldg(&x2[r1]);
        const float s0 = -2.0f * __ldg(&sx[r0]);
        const float s1 = -2.0f * __ldg(&sx[r1]);
        #pragma unroll
        for (int j = 0; j < 4; j++) {
            const int col = n_base + wn * 32 + j * 8 + q * 2;
            const float cA = __ldg(&c2[col]);
            const float cB = __ldg(&c2[col + 1]);
            const float scA = __ldg(&sc[col]);
            const float scB = __ldg(&sc[col + 1]);
            float2 v0, v1;
            v0.x = fmaf(s0 * scA, (float)acc[i][j][0], x0 + cA);
            v0.y = fmaf(s0 * scB, (float)acc[i][j][1], x0 + cB);
            v1.x = fmaf(s1 * scA, (float)acc[i][j][2], x1 + cA);
            v1.y = fmaf(s1 * scB, (float)acc[i][j][3], x1 + cB);
            *reinterpret_cast<float2*>(&out[(size_t)r0 * C_ROWS + col]) = v0;
            *reinterpret_cast<float2*>(&out[(size_t)r1 * C_ROWS + col]) = v1;
        }
    }
}

// ---------------- host launch ----------------
extern "C" void kernel_launch(void* const* d_in, const int* in_sizes, int n_in,
                              void* d_out, int out_size) {
    (void)in_sizes; (void)n_in; (void)out_size;
    const float* feat = (const float*)d_in[0];
    const float* cent = (const float*)d_in[1];
    float* out = (float*)d_out;

    void *p_fq = nullptr, *p_cq = nullptr, *p_x2 = nullptr, *p_c2 = nullptr;
    void *p_sx = nullptr, *p_sc = nullptr;
    cudaGetSymbolAddress(&p_fq, g_featq);
    cudaGetSymbolAddress(&p_cq, g_centq);
    cudaGetSymbolAddress(&p_x2, g_x2);
    cudaGetSymbolAddress(&p_c2, g_c2);
    cudaGetSymbolAddress(&p_sx, g_sx);
    cudaGetSymbolAddress(&p_sc, g_sc);

    prep_kernel<<<B_ROWS, 256>>>(feat, (uint8_t*)p_fq, (float*)p_x2, (float*)p_sx);
    prep_kernel<<<C_ROWS, 256>>>(cent, (uint8_t*)p_cq, (float*)p_c2, (float*)p_sc);

    cudaFuncSetAttribute(dist_gemm_kernel,
                         cudaFuncAttributeMaxDynamicSharedMemorySize, SMEM_BYTES);

    int grid = (B_ROWS / BM) * (C_ROWS / BN);   // 4096
    dist_gemm_kernel<<<grid, 256, SMEM_BYTES>>>(
        (const uint8_t*)p_fq, (const uint8_t*)p_cq,
        (const float*)p_x2, (const float*)p_c2,
        (const float*)p_sx, (const float*)p_sc, out);
}

// round 4
// speedup vs baseline: 1.6446x; 1.6446x over previous
#include <cuda_runtime.h>
#include <cuda_bf16.h>
#include <cstdint>

// ---------------- problem shape ----------------
static constexpr int B_ROWS = 16384;
static constexpr int C_ROWS = 4096;
static constexpr int KDIM   = 1024;

// ---------------- GEMM tiling (int8) ----------------
static constexpr int BM = 128;
static constexpr int BN = 128;
static constexpr int BK = 128;                // int8 elems (=bytes) per K-chunk
static constexpr int STAGES = 3;
static constexpr int KTILES = KDIM / BK;      // 8
static constexpr int KSTEPS = BK / 32;        // 4 imma k-steps (k32) per chunk

// padded smem rows: 128 + 16 bytes -> 144B stride (conflict-free ldmatrix)
static constexpr int ROW_B   = BK + 16;       // 144 bytes
static constexpr int TILE_B  = 128 * ROW_B;   // 18432 bytes per (A or B) stage
static constexpr int OFF_B0  = STAGES * TILE_B;
static constexpr int SMEM_BYTES = 2 * STAGES * TILE_B;  // 110592

// ---------------- device scratch (no cudaMalloc allowed) ----------------
__device__ uint8_t g_featq[(size_t)B_ROWS * KDIM];
__device__ uint8_t g_centq[(size_t)C_ROWS * KDIM];
__device__ float g_x2[B_ROWS];
__device__ float g_c2[C_ROWS];
__device__ float g_sx[B_ROWS];
__device__ float g_sc[C_ROWS];

// ---------------- PTX helpers ----------------
__device__ __forceinline__ uint32_t smem_u32(const void* p) {
    uint32_t a;
    asm("{ .reg .u64 t; cvta.to.shared.u64 t, %1; cvt.u32.u64 %0, t; }"
        : "=r"(a) : "l"(p));
    return a;
}

__device__ __forceinline__ void cp_async16(uint32_t s_addr, const void* g_addr) {
    asm volatile("cp.async.cg.shared.global [%0], [%1], 16;"
                 :: "r"(s_addr), "l"(g_addr) : "memory");
}
__device__ __forceinline__ void cp_commit() {
    asm volatile("cp.async.commit_group;" ::: "memory");
}
template <int N>
__device__ __forceinline__ void cp_wait() {
    asm volatile("cp.async.wait_group %0;" :: "n"(N) : "memory");
}

__device__ __forceinline__ void ldsm_x4(uint32_t& r0, uint32_t& r1, uint32_t& r2, uint32_t& r3,
                                        uint32_t addr) {
    asm volatile("ldmatrix.sync.aligned.m8n8.x4.shared.b16 {%0,%1,%2,%3}, [%4];"
                 : "=r"(r0), "=r"(r1), "=r"(r2), "=r"(r3) : "r"(addr));
}

// int8 IMMA m16n8k32, s32 accumulate
__device__ __forceinline__ void imma16832(int* d, uint32_t a0, uint32_t a1, uint32_t a2,
                                          uint32_t a3, uint32_t b0, uint32_t b1) {
    asm volatile(
        "mma.sync.aligned.m16n8k32.row.col.s32.s8.s8.s32 "
        "{%0,%1,%2,%3}, {%4,%5,%6,%7}, {%8,%9}, {%0,%1,%2,%3};"
        : "+r"(d[0]), "+r"(d[1]), "+r"(d[2]), "+r"(d[3])
        : "r"(a0), "r"(a1), "r"(a2), "r"(a3), "r"(b0), "r"(b1));
}

// ---------------- prep: fp32 -> int8 (per-row symmetric) + row sum-of-squares ----------------
__global__ __launch_bounds__(256)
void prep_kernel(const float* __restrict__ in, uint8_t* __restrict__ outq,
                 float* __restrict__ sq, float* __restrict__ scale) {
    int row = blockIdx.x;
    int t = threadIdx.x;
    float4 v = reinterpret_cast<const float4*>(in)[(size_t)row * 256 + t];

    float s = fmaf(v.x, v.x, fmaf(v.y, v.y, fmaf(v.z, v.z, v.w * v.w)));
    float m = fmaxf(fmaxf(fabsf(v.x), fabsf(v.y)), fmaxf(fabsf(v.z), fabsf(v.w)));
    #pragma unroll
    for (int o = 16; o > 0; o >>= 1) {
        s += __shfl_xor_sync(0xFFFFFFFFu, s, o);
        m = fmaxf(m, __shfl_xor_sync(0xFFFFFFFFu, m, o));
    }
    __shared__ float ws[8], wm[8];
    __shared__ float fin_m;
    if ((t & 31) == 0) { ws[t >> 5] = s; wm[t >> 5] = m; }
    __syncthreads();
    if (t < 8) {
        float x = ws[t], y = wm[t];
        #pragma unroll
        for (int o = 4; o > 0; o >>= 1) {
            x += __shfl_xor_sync(0xFFu, x, o);
            y = fmaxf(y, __shfl_xor_sync(0xFFu, y, o));
        }
        if (t == 0) {
            fin_m = (y > 0.0f) ? y : 1.0f;
            sq[row] = x;
            scale[row] = fin_m * (1.0f / 127.0f);
        }
    }
    __syncthreads();

    float inv = 127.0f / fin_m;
    int q0 = max(-127, min(127, __float2int_rn(v.x * inv)));
    int q1 = max(-127, min(127, __float2int_rn(v.y * inv)));
    int q2 = max(-127, min(127, __float2int_rn(v.z * inv)));
    int q3 = max(-127, min(127, __float2int_rn(v.w * inv)));
    uint32_t packed = (uint32_t)(q0 & 0xFF) | ((uint32_t)(q1 & 0xFF) << 8) |
                      ((uint32_t)(q2 & 0xFF) << 16) | ((uint32_t)(q3 & 0xFF) << 24);
    reinterpret_cast<uint32_t*>(outq)[(size_t)row * 256 + t] = packed;
}

// ---------------- main int8 GEMM + fused distance epilogue ----------------
// NOTE: launch_bounds (256, 1) — the (256, 2) variant capped regs at 128 and
// spilled the 64-reg accumulator to local memory (round-3 3x regression).
__global__ __launch_bounds__(256, 1)
void dist_gemm_kernel(const uint8_t* __restrict__ Aq,
                      const uint8_t* __restrict__ Bq,
                      const float* __restrict__ x2,
                      const float* __restrict__ c2,
                      const float* __restrict__ sx,
                      const float* __restrict__ sc,
                      float* __restrict__ out) {
    extern __shared__ char smem[];
    const uint32_t sb = smem_u32(smem);
    const int tid = threadIdx.x;
    const int wid = tid >> 5;
    const int lane = tid & 31;

    // n-fast tile mapping for L2 reuse of the A (feat) tile across a wave
    const int nt = blockIdx.x & 31;           // 32 n-tiles
    const int mt = blockIdx.x >> 5;           // 128 m-tiles
    const int m_base = mt * BM;
    const int n_base = nt * BN;

    // cp.async: 8 x 16B chunks per 128B row; 1024 chunks per stage; 4/thread
    auto load_stage = [&](int s, int kt) {
        const uint32_t sA = sb + s * TILE_B;
        const uint32_t sB = sb + OFF_B0 + s * TILE_B;
        const uint8_t* gA = Aq + (size_t)m_base * KDIM + kt * BK;
        const uint8_t* gB = Bq + (size_t)n_base * KDIM + kt * BK;
        #pragma unroll
        for (int i = 0; i < 4; i++) {
            int cid = tid + i * 256;
            int row = cid >> 3, c = cid & 7;
            cp_async16(sA + row * ROW_B + c * 16, gA + (size_t)row * KDIM + c * 16);
        }
        #pragma unroll
        for (int i = 0; i < 4; i++) {
            int cid = tid + i * 256;
            int row = cid >> 3, c = cid & 7;
            cp_async16(sB + row * ROW_B + c * 16, gB + (size_t)row * KDIM + c * 16);
        }
    };

    // warp tiling: 2 (M) x 4 (N); each warp 64x32
    const int wm = wid >> 2;                  // 0..1
    const int wn = wid & 3;                   // 0..3

    int acc[4][4][4];                         // [mtile][ntile][frag]
    #pragma unroll
    for (int i = 0; i < 4; i++)
        #pragma unroll
        for (int j = 0; j < 4; j++)
            #pragma unroll
            for (int f = 0; f < 4; f++) acc[i][j][f] = 0;

    // ldmatrix lane address components (byte units)
    const int a_row_l = (lane & 15);             // rows 0-15 within 16-row group
    const int a_koff  = (lane >> 4) * 16;        // k-byte group 0 / 16
    const int b_koff  = ((lane >> 3) & 1) * 16;  // k-byte group 0 / 16

    // prologue: fill 3 stages
    load_stage(0, 0); cp_commit();
    load_stage(1, 1); cp_commit();
    load_stage(2, 2); cp_commit();

    #pragma unroll 1
    for (int kt = 0; kt < KTILES; kt++) {
        const int s = kt % STAGES;
        cp_wait<2>();
        __syncthreads();

        const uint32_t sA = sb + s * TILE_B;
        const uint32_t sB = sb + OFF_B0 + s * TILE_B;

        #pragma unroll
        for (int kk = 0; kk < KSTEPS; kk++) {
            const int k0 = kk * 32;              // 32 int8 per k-step
            // A frags (4 mtiles of 16 rows)
            uint32_t af[4][4];
            #pragma unroll
            for (int i = 0; i < 4; i++) {
                int row = wm * 64 + i * 16 + a_row_l;
                uint32_t addr = sA + row * ROW_B + k0 + a_koff;
                ldsm_x4(af[i][0], af[i][1], af[i][2], af[i][3], addr);
            }
            // B frags (4 ntiles via 2 x4-ldmatrix)
            uint32_t bf[4][2];
            #pragma unroll
            for (int j = 0; j < 2; j++) {
                int n = wn * 32 + (2 * j + (lane >> 4)) * 8 + (lane & 7);
                uint32_t addr = sB + n * ROW_B + k0 + b_koff;
                uint32_t r0, r1, r2, r3;
                ldsm_x4(r0, r1, r2, r3, addr);
                bf[2 * j][0] = r0; bf[2 * j][1] = r1;
                bf[2 * j + 1][0] = r2; bf[2 * j + 1][1] = r3;
            }
            // 16 IMMA
            #pragma unroll
            for (int i = 0; i < 4; i++)
                #pragma unroll
                for (int j = 0; j < 4; j++)
                    imma16832(acc[i][j], af[i][0], af[i][1], af[i][2], af[i][3],
                              bf[j][0], bf[j][1]);
        }

        __syncthreads();
        if (kt + STAGES < KTILES) load_stage(s, kt + STAGES);
        cp_commit();
    }

    // ---------------- epilogue: dist = x2[m] + c2[n] - 2*sx*sc*acc ----------------
    const int g = lane >> 2;          // row group 0..7
    const int q = lane & 3;           // col quad
    #pragma unroll
    for (int i = 0; i < 4; i++) {
        const int r0 = m_base + wm * 64 + i * 16 + g;
        const int r1 = r0 + 8;
        const float x0 = __ldg(&x2[r0]);
        const float x1 = __ldg(&x2[r1]);
        const float s0 = -2.0f * __ldg(&sx[r0]);
        const float s1 = -2.0f * __ldg(&sx[r1]);
        #pragma unroll
        for (int j = 0; j < 4; j++) {
            const int col = n_base + wn * 32 + j * 8 + q * 2;
            const float cA = __ldg(&c2[col]);
            const float cB = __ldg(&c2[col + 1]);
            const float scA = __ldg(&sc[col]);
            const float scB = __ldg(&sc[col + 1]);
            float2 v0, v1;
            v0.x = fmaf(s0 * scA, (float)acc[i][j][0], x0 + cA);
            v0.y = fmaf(s0 * scB, (float)acc[i][j][1], x0 + cB);
            v1.x = fmaf(s1 * scA, (float)acc[i][j][2], x1 + cA);
            v1.y = fmaf(s1 * scB, (float)acc[i][j][3], x1 + cB);
            *reinterpret_cast<float2*>(&out[(size_t)r0 * C_ROWS + col]) = v0;
            *reinterpret_cast<float2*>(&out[(size_t)r1 * C_ROWS + col]) = v1;
        }
    }
}

// ---------------- host launch ----------------
extern "C" void kernel_launch(void* const* d_in, const int* in_sizes, int n_in,
                              void* d_out, int out_size) {
    (void)in_sizes; (void)n_in; (void)out_size;
    const float* feat = (const float*)d_in[0];
    const float* cent = (const float*)d_in[1];
    float* out = (float*)d_out;

    void *p_fq = nullptr, *p_cq = nullptr, *p_x2 = nullptr, *p_c2 = nullptr;
    void *p_sx = nullptr, *p_sc = nullptr;
    cudaGetSymbolAddress(&p_fq, g_featq);
    cudaGetSymbolAddress(&p_cq, g_centq);
    cudaGetSymbolAddress(&p_x2, g_x2);
    cudaGetSymbolAddress(&p_c2, g_c2);
    cudaGetSymbolAddress(&p_sx, g_sx);
    cudaGetSymbolAddress(&p_sc, g_sc);

    prep_kernel<<<B_ROWS, 256>>>(feat, (uint8_t*)p_fq, (float*)p_x2, (float*)p_sx);
    prep_kernel<<<C_ROWS, 256>>>(cent, (uint8_t*)p_cq, (float*)p_c2, (float*)p_sc);

    cudaFuncSetAttribute(dist_gemm_kernel,
                         cudaFuncAttributeMaxDynamicSharedMemorySize, SMEM_BYTES);

    int grid = (B_ROWS / BM) * (C_ROWS / BN);   // 4096
    dist_gemm_kernel<<<grid, 256, SMEM_BYTES>>>(
        (const uint8_t*)p_fq, (const uint8_t*)p_cq,
        (const float*)p_x2, (const float*)p_c2,
        (const float*)p_sx, (const float*)p_sc, out);
}

// round 5
// speedup vs baseline: 3.1221x; 1.8983x over previous
#include <cuda_runtime.h>
#include <cuda_bf16.h>
#include <cstdint>

// ---------------- problem shape ----------------
static constexpr int B_ROWS = 16384;
static constexpr int C_ROWS = 4096;
static constexpr int KDIM   = 1024;

// ---------------- GEMM tiling (bf16) ----------------
static constexpr int BM = 128;
static constexpr int BN = 128;
static constexpr int BK = 64;                 // bf16 elems per K-chunk
static constexpr int STAGES = 4;              // 4 stages -> single barrier per k-tile
static constexpr int KTILES = KDIM / BK;      // 16
static constexpr int KSTEPS = BK / 16;        // 4 mma k-steps per chunk

// padded smem rows: 64 + 8 halves -> 144B stride (conflict-free ldmatrix)
static constexpr int ROW_H   = BK + 8;        // 72 halves
static constexpr int TILE_B  = 128 * ROW_H * 2;   // 18432 bytes per (A or B) stage
static constexpr int OFF_B0  = STAGES * TILE_B;
static constexpr int SMEM_BYTES = 2 * STAGES * TILE_B;  // 147456

// ---------------- device scratch (no cudaMalloc allowed) ----------------
__device__ __nv_bfloat16 g_featb[(size_t)B_ROWS * KDIM];
__device__ __nv_bfloat16 g_centb[(size_t)C_ROWS * KDIM];
__device__ float g_x2[B_ROWS];
__device__ float g_c2[C_ROWS];

// ---------------- PTX helpers ----------------
__device__ __forceinline__ uint32_t smem_u32(const void* p) {
    uint32_t a;
    asm("{ .reg .u64 t; cvta.to.shared.u64 t, %1; cvt.u32.u64 %0, t; }"
        : "=r"(a) : "l"(p));
    return a;
}

__device__ __forceinline__ void cp_async16(uint32_t s_addr, const void* g_addr) {
    asm volatile("cp.async.cg.shared.global [%0], [%1], 16;"
                 :: "r"(s_addr), "l"(g_addr) : "memory");
}
__device__ __forceinline__ void cp_commit() {
    asm volatile("cp.async.commit_group;" ::: "memory");
}
template <int N>
__device__ __forceinline__ void cp_wait() {
    asm volatile("cp.async.wait_group %0;" :: "n"(N) : "memory");
}

__device__ __forceinline__ void ldsm_x4(uint32_t& r0, uint32_t& r1, uint32_t& r2, uint32_t& r3,
                                        uint32_t addr) {
    asm volatile("ldmatrix.sync.aligned.m8n8.x4.shared.b16 {%0,%1,%2,%3}, [%4];"
                 : "=r"(r0), "=r"(r1), "=r"(r2), "=r"(r3) : "r"(addr));
}

__device__ __forceinline__ void mma16816(float* d, uint32_t a0, uint32_t a1, uint32_t a2,
                                         uint32_t a3, uint32_t b0, uint32_t b1) {
    asm volatile(
        "mma.sync.aligned.m16n8k16.row.col.f32.bf16.bf16.f32 "
        "{%0,%1,%2,%3}, {%4,%5,%6,%7}, {%8,%9}, {%0,%1,%2,%3};"
        : "+f"(d[0]), "+f"(d[1]), "+f"(d[2]), "+f"(d[3])
        : "r"(a0), "r"(a1), "r"(a2), "r"(a3), "r"(b0), "r"(b1));
}

// ---------------- fused prep: fp32 -> bf16 + row sum-of-squares (feat AND cent) ----------------
__global__ __launch_bounds__(256)
void prep_kernel(const float* __restrict__ feat, const float* __restrict__ cent) {
    int blk = blockIdx.x;
    const float* in;
    __nv_bfloat16* outbf;
    float* sq;
    int row;
    if (blk < B_ROWS) {
        row = blk; in = feat; outbf = g_featb; sq = g_x2;
    } else {
        row = blk - B_ROWS; in = cent; outbf = g_centb; sq = g_c2;
    }
    int t = threadIdx.x;
    float4 v = reinterpret_cast<const float4*>(in)[(size_t)row * 256 + t];

    float s = fmaf(v.x, v.x, fmaf(v.y, v.y, fmaf(v.z, v.z, v.w * v.w)));
    #pragma unroll
    for (int o = 16; o > 0; o >>= 1) s += __shfl_xor_sync(0xFFFFFFFFu, s, o);
    __shared__ float ws[8];
    if ((t & 31) == 0) ws[t >> 5] = s;
    __syncthreads();
    if (t < 8) {
        float x = ws[t];
        #pragma unroll
        for (int o = 4; o > 0; o >>= 1) x += __shfl_xor_sync(0xFFu, x, o);
        if (t == 0) sq[row] = x;
    }

    union { __nv_bfloat162 h2[2]; uint2 u; } pk;
    pk.h2[0] = __floats2bfloat162_rn(v.x, v.y);
    pk.h2[1] = __floats2bfloat162_rn(v.z, v.w);
    reinterpret_cast<uint2*>(outbf)[(size_t)row * 256 + t] = pk.u;
}

// ---------------- main bf16 GEMM + fused distance epilogue ----------------
__global__ __launch_bounds__(256, 1)
void dist_gemm_kernel(const __nv_bfloat16* __restrict__ Abf,
                      const __nv_bfloat16* __restrict__ Bbf,
                      const float* __restrict__ x2,
                      const float* __restrict__ c2,
                      float* __restrict__ out) {
    extern __shared__ char smem[];
    const uint32_t sb = smem_u32(smem);
    const int tid = threadIdx.x;
    const int wid = tid >> 5;
    const int lane = tid & 31;

    // n-fast tile mapping for L2 reuse of the A (feat) tile across a wave
    const int nt = blockIdx.x & 31;           // 32 n-tiles
    const int mt = blockIdx.x >> 5;           // 128 m-tiles
    const int m_base = mt * BM;
    const int n_base = nt * BN;

    // cp.async load mapping: 4 x 16B chunks per thread per (A or B) stage
    auto load_stage = [&](int s, int kt) {
        const uint32_t sA = sb + s * TILE_B;
        const uint32_t sB = sb + OFF_B0 + s * TILE_B;
        const __nv_bfloat16* gA = Abf + (size_t)m_base * KDIM + kt * BK;
        const __nv_bfloat16* gB = Bbf + (size_t)n_base * KDIM + kt * BK;
        #pragma unroll
        for (int i = 0; i < 4; i++) {
            int cid = tid + i * 256;
            int row = cid >> 3, c = cid & 7;
            cp_async16(sA + row * (ROW_H * 2) + c * 16, gA + (size_t)row * KDIM + c * 8);
        }
        #pragma unroll
        for (int i = 0; i < 4; i++) {
            int cid = tid + i * 256;
            int row = cid >> 3, c = cid & 7;
            cp_async16(sB + row * (ROW_H * 2) + c * 16, gB + (size_t)row * KDIM + c * 8);
        }
    };

    // warp tiling: 2 (M) x 4 (N); each warp 64x32
    const int wm = wid >> 2;                  // 0..1
    const int wn = wid & 3;                   // 0..3

    float acc[4][4][4];                       // [mtile][ntile][frag]
    #pragma unroll
    for (int i = 0; i < 4; i++)
        #pragma unroll
        for (int j = 0; j < 4; j++)
            #pragma unroll
            for (int f = 0; f < 4; f++) acc[i][j][f] = 0.0f;

    // ldmatrix lane address components
    const int a_row_l = (lane & 15);
    const int a_koff  = (lane >> 4) * 8;         // halves
    const int b_koff  = ((lane >> 3) & 1) * 8;   // halves

    // prologue: fill 3 of 4 stages
    load_stage(0, 0); cp_commit();
    load_stage(1, 1); cp_commit();
    load_stage(2, 2); cp_commit();

    #pragma unroll 1
    for (int kt = 0; kt < KTILES; kt++) {
        const int s = kt % STAGES;
        cp_wait<2>();
        __syncthreads();        // single barrier: group kt visible to all; stage
                                // (kt+3)%4 was consumed at kt-1 by all warps

        // issue next load immediately so it overlaps this tile's math
        if (kt + 3 < KTILES) load_stage((kt + 3) % STAGES, kt + 3);
        cp_commit();

        const uint32_t sA = sb + s * TILE_B;
        const uint32_t sB = sb + OFF_B0 + s * TILE_B;

        #pragma unroll
        for (int kk = 0; kk < KSTEPS; kk++) {
            const int k0 = kk * 16;
            uint32_t af[4][4];
            #pragma unroll
            for (int i = 0; i < 4; i++) {
                int row = wm * 64 + i * 16 + a_row_l;
                uint32_t addr = sA + row * (ROW_H * 2) + (k0 + a_koff) * 2;
                ldsm_x4(af[i][0], af[i][1], af[i][2], af[i][3], addr);
            }
            uint32_t bf[4][2];
            #pragma unroll
            for (int j = 0; j < 2; j++) {
                int n = wn * 32 + (2 * j + (lane >> 4)) * 8 + (lane & 7);
                uint32_t addr = sB + n * (ROW_H * 2) + (k0 + b_koff) * 2;
                uint32_t r0, r1, r2, r3;
                ldsm_x4(r0, r1, r2, r3, addr);
                bf[2 * j][0] = r0; bf[2 * j][1] = r1;
                bf[2 * j + 1][0] = r2; bf[2 * j + 1][1] = r3;
            }
            #pragma unroll
            for (int i = 0; i < 4; i++)
                #pragma unroll
                for (int j = 0; j < 4; j++)
                    mma16816(acc[i][j], af[i][0], af[i][1], af[i][2], af[i][3],
                             bf[j][0], bf[j][1]);
        }
    }

    // ---------------- epilogue: dist = x2[m] + c2[n] - 2*acc ----------------
    const int g = lane >> 2;
    const int q = lane & 3;
    #pragma unroll
    for (int i = 0; i < 4; i++) {
        const int r0 = m_base + wm * 64 + i * 16 + g;
        const int r1 = r0 + 8;
        const float x0 = __ldg(&x2[r0]);
        const float x1 = __ldg(&x2[r1]);
        #pragma unroll
        for (int j = 0; j < 4; j++) {
            const int col = n_base + wn * 32 + j * 8 + q * 2;
            const float cA = __ldg(&c2[col]);
            const float cB = __ldg(&c2[col + 1]);
            float2 v0, v1;
            v0.x = fmaf(-2.0f, acc[i][j][0], x0 + cA);
            v0.y = fmaf(-2.0f, acc[i][j][1], x0 + cB);
            v1.x = fmaf(-2.0f, acc[i][j][2], x1 + cA);
            v1.y = fmaf(-2.0f, acc[i][j][3], x1 + cB);
            *reinterpret_cast<float2*>(&out[(size_t)r0 * C_ROWS + col]) = v0;
            *reinterpret_cast<float2*>(&out[(size_t)r1 * C_ROWS + col]) = v1;
        }
    }
}

// ---------------- host launch ----------------
extern "C" void kernel_launch(void* const* d_in, const int* in_sizes, int n_in,
                              void* d_out, int out_size) {
    (void)in_sizes; (void)n_in; (void)out_size;
    const float* feat = (const float*)d_in[0];
    const float* cent = (const float*)d_in[1];
    float* out = (float*)d_out;

    void *p_fb = nullptr, *p_cb = nullptr, *p_x2 = nullptr, *p_c2 = nullptr;
    cudaGetSymbolAddress(&p_fb, g_featb);
    cudaGetSymbolAddress(&p_cb, g_centb);
    cudaGetSymbolAddress(&p_x2, g_x2);
    cudaGetSymbolAddress(&p_c2, g_c2);

    prep_kernel<<<B_ROWS + C_ROWS, 256>>>(feat, cent);

    cudaFuncSetAttribute(dist_gemm_kernel,
                         cudaFuncAttributeMaxDynamicSharedMemorySize, SMEM_BYTES);

    int grid = (B_ROWS / BM) * (C_ROWS / BN);   // 4096
    dist_gemm_kernel<<<grid, 256, SMEM_BYTES>>>(
        (const __nv_bfloat16*)p_fb, (const __nv_bfloat16*)p_cb,
        (const float*)p_x2, (const float*)p_c2, out);
}

// round 6
// speedup vs baseline: 3.8434x; 1.2310x over previous
#include <cuda_runtime.h>
#include <cuda_bf16.h>
#include <cstdint>

// ---------------- problem shape ----------------
static constexpr int B_ROWS = 16384;
static constexpr int C_ROWS = 4096;
static constexpr int KDIM   = 1024;

// ---------------- GEMM tiling (bf16) ----------------
static constexpr int BM = 128;
static constexpr int BN = 128;
static constexpr int BK = 64;                 // bf16 elems per K-chunk
static constexpr int STAGES = 3;              // 110.6KB -> 2 CTAs/SM (221KB of 228KB)
static constexpr int KTILES = KDIM / BK;      // 16
static constexpr int KSTEPS = BK / 16;        // 4 mma k-steps per chunk

// padded smem rows: 64 + 8 halves -> 144B stride (conflict-free ldmatrix)
static constexpr int ROW_H   = BK + 8;        // 72 halves
static constexpr int TILE_B  = 128 * ROW_H * 2;   // 18432 bytes per (A or B) stage
static constexpr int OFF_B0  = STAGES * TILE_B;
static constexpr int SMEM_BYTES = 2 * STAGES * TILE_B;  // 110592

// ---------------- device scratch (no cudaMalloc allowed) ----------------
__device__ __nv_bfloat16 g_featb[(size_t)B_ROWS * KDIM];
__device__ __nv_bfloat16 g_centb[(size_t)C_ROWS * KDIM];
__device__ float g_x2[B_ROWS];
__device__ float g_c2[C_ROWS];

// ---------------- PTX helpers ----------------
__device__ __forceinline__ uint32_t smem_u32(const void* p) {
    uint32_t a;
    asm("{ .reg .u64 t; cvta.to.shared.u64 t, %1; cvt.u32.u64 %0, t; }"
        : "=r"(a) : "l"(p));
    return a;
}

__device__ __forceinline__ void cp_async16(uint32_t s_addr, const void* g_addr) {
    asm volatile("cp.async.cg.shared.global [%0], [%1], 16;"
                 :: "r"(s_addr), "l"(g_addr) : "memory");
}
__device__ __forceinline__ void cp_commit() {
    asm volatile("cp.async.commit_group;" ::: "memory");
}
template <int N>
__device__ __forceinline__ void cp_wait() {
    asm volatile("cp.async.wait_group %0;" :: "n"(N) : "memory");
}

__device__ __forceinline__ void ldsm_x4(uint32_t& r0, uint32_t& r1, uint32_t& r2, uint32_t& r3,
                                        uint32_t addr) {
    asm volatile("ldmatrix.sync.aligned.m8n8.x4.shared.b16 {%0,%1,%2,%3}, [%4];"
                 : "=r"(r0), "=r"(r1), "=r"(r2), "=r"(r3) : "r"(addr));
}

__device__ __forceinline__ void mma16816(float* d, uint32_t a0, uint32_t a1, uint32_t a2,
                                         uint32_t a3, uint32_t b0, uint32_t b1) {
    asm volatile(
        "mma.sync.aligned.m16n8k16.row.col.f32.bf16.bf16.f32 "
        "{%0,%1,%2,%3}, {%4,%5,%6,%7}, {%8,%9}, {%0,%1,%2,%3};"
        : "+f"(d[0]), "+f"(d[1]), "+f"(d[2]), "+f"(d[3])
        : "r"(a0), "r"(a1), "r"(a2), "r"(a3), "r"(b0), "r"(b1));
}

// ---------------- fused prep: fp32 -> bf16 + row sum-of-squares (feat AND cent) ----------------
__global__ __launch_bounds__(256)
void prep_kernel(const float* __restrict__ feat, const float* __restrict__ cent) {
    int blk = blockIdx.x;
    const float* in;
    __nv_bfloat16* outbf;
    float* sq;
    int row;
    if (blk < B_ROWS) {
        row = blk; in = feat; outbf = g_featb; sq = g_x2;
    } else {
        row = blk - B_ROWS; in = cent; outbf = g_centb; sq = g_c2;
    }
    int t = threadIdx.x;
    float4 v = reinterpret_cast<const float4*>(in)[(size_t)row * 256 + t];

    float s = fmaf(v.x, v.x, fmaf(v.y, v.y, fmaf(v.z, v.z, v.w * v.w)));
    #pragma unroll
    for (int o = 16; o > 0; o >>= 1) s += __shfl_xor_sync(0xFFFFFFFFu, s, o);
    __shared__ float ws[8];
    if ((t & 31) == 0) ws[t >> 5] = s;
    __syncthreads();
    if (t < 8) {
        float x = ws[t];
        #pragma unroll
        for (int o = 4; o > 0; o >>= 1) x += __shfl_xor_sync(0xFFu, x, o);
        if (t == 0) sq[row] = x;
    }

    union { __nv_bfloat162 h2[2]; uint2 u; } pk;
    pk.h2[0] = __floats2bfloat162_rn(v.x, v.y);
    pk.h2[1] = __floats2bfloat162_rn(v.z, v.w);
    reinterpret_cast<uint2*>(outbf)[(size_t)row * 256 + t] = pk.u;
}

// ---------------- main bf16 GEMM + fused distance epilogue ----------------
// (256, 2): 2 CTAs/SM -> 4 warps/SMSP to cover LDSM->HMMA latency.
// Inner loop restructured so live regs (~100) stay under the 128 cap: B frags
// (8 regs) loaded once per k-step, A frags (4 regs) loaded per-mtile and
// consumed immediately.
__global__ __launch_bounds__(256, 2)
void dist_gemm_kernel(const __nv_bfloat16* __restrict__ Abf,
                      const __nv_bfloat16* __restrict__ Bbf,
                      const float* __restrict__ x2,
                      const float* __restrict__ c2,
                      float* __restrict__ out) {
    extern __shared__ char smem[];
    const uint32_t sb = smem_u32(smem);
    const int tid = threadIdx.x;
    const int wid = tid >> 5;
    const int lane = tid & 31;

    // n-fast tile mapping for L2 reuse of the A (feat) tile across a wave
    const int nt = blockIdx.x & 31;           // 32 n-tiles
    const int mt = blockIdx.x >> 5;           // 128 m-tiles
    const int m_base = mt * BM;
    const int n_base = nt * BN;

    // cp.async: 4 x 16B chunks per thread per (A or B) stage.
    // Incremental global pointers (advance by BK per k-tile) to minimize regs.
    const int ld_row = tid >> 3;              // uses chunks tid, tid+256, ... (rows +32)
    const int ld_c16 = (tid & 7) * 16;        // byte offset within 128B row
    const __nv_bfloat16* gA = Abf + (size_t)(m_base + ld_row) * KDIM + (tid & 7) * 8;
    const __nv_bfloat16* gB = Bbf + (size_t)(n_base + ld_row) * KDIM + (tid & 7) * 8;
    const uint32_t sA0 = sb + ld_row * (ROW_H * 2) + ld_c16;
    const uint32_t sB0 = sb + OFF_B0 + ld_row * (ROW_H * 2) + ld_c16;

    auto load_stage = [&](int s, int kt) {
        const uint32_t stA = sA0 + s * TILE_B;
        const uint32_t stB = sB0 + s * TILE_B;
        const size_t gk = (size_t)kt * BK;
        #pragma unroll
        for (int i = 0; i < 4; i++)
            cp_async16(stA + i * 32 * (ROW_H * 2), gA + gk + (size_t)i * 32 * KDIM);
        #pragma unroll
        for (int i = 0; i < 4; i++)
            cp_async16(stB + i * 32 * (ROW_H * 2), gB + gk + (size_t)i * 32 * KDIM);
    };

    // warp tiling: 2 (M) x 4 (N); each warp 64x32
    const int wm = wid >> 2;                  // 0..1
    const int wn = wid & 3;                   // 0..3

    float acc[4][4][4];                       // [mtile][ntile][frag]
    #pragma unroll
    for (int i = 0; i < 4; i++)
        #pragma unroll
        for (int j = 0; j < 4; j++)
            #pragma unroll
            for (int f = 0; f < 4; f++) acc[i][j][f] = 0.0f;

    // ldmatrix lane address components (byte offsets within a stage)
    const uint32_t a_addr0 = (uint32_t)((wm * 64 + (lane & 15)) * (ROW_H * 2) + (lane >> 4) * 16);
    const uint32_t b_addr0 = (uint32_t)((wn * 32 + (lane >> 4) * 8 + (lane & 7)) * (ROW_H * 2)
                                        + ((lane >> 3) & 1) * 16);

    // prologue: fill 2 of 3 stages
    load_stage(0, 0); cp_commit();
    load_stage(1, 1); cp_commit();

    #pragma unroll 1
    for (int kt = 0; kt < KTILES; kt++) {
        const int s = kt % STAGES;
        cp_wait<1>();
        __syncthreads();        // stage kt visible; stage (kt+2)%3 drained at kt-1

        if (kt + 2 < KTILES) { load_stage((kt + 2) % STAGES, kt + 2); }
        cp_commit();

        const uint32_t sAs = sb + s * TILE_B;
        const uint32_t sBs = sb + OFF_B0 + s * TILE_B;

        #pragma unroll
        for (int kk = 0; kk < KSTEPS; kk++) {
            const uint32_t k0b = kk * 32;     // k-step byte offset (16 halves)
            // B frags first (8 regs, live across mtiles)
            uint32_t bf[4][2];
            {
                uint32_t r0, r1, r2, r3;
                ldsm_x4(r0, r1, r2, r3, sBs + b_addr0 + k0b);
                bf[0][0] = r0; bf[0][1] = r1; bf[1][0] = r2; bf[1][1] = r3;
                ldsm_x4(r0, r1, r2, r3, sBs + b_addr0 + 16 * (ROW_H * 2) + k0b);
                bf[2][0] = r0; bf[2][1] = r1; bf[3][0] = r2; bf[3][1] = r3;
            }
            // per-mtile: load A quad, use immediately (4 live regs)
            #pragma unroll
            for (int i = 0; i < 4; i++) {
                uint32_t a0, a1, a2, a3;
                ldsm_x4(a0, a1, a2, a3, sAs + a_addr0 + i * 16 * (ROW_H * 2) + k0b);
                #pragma unroll
                for (int j = 0; j < 4; j++)
                    mma16816(acc[i][j], a0, a1, a2, a3, bf[j][0], bf[j][1]);
            }
        }
    }

    // ---------------- epilogue: dist = x2[m] + c2[n] - 2*acc ----------------
    const int g = lane >> 2;
    const int q = lane & 3;
    #pragma unroll
    for (int i = 0; i < 4; i++) {
        const int r0 = m_base + wm * 64 + i * 16 + g;
        const int r1 = r0 + 8;
        const float x0 = __ldg(&x2[r0]);
        const float x1 = __ldg(&x2[r1]);
        #pragma unroll
        for (int j = 0; j < 4; j++) {
            const int col = n_base + wn * 32 + j * 8 + q * 2;
            const float cA = __ldg(&c2[col]);
            const float cB = __ldg(&c2[col + 1]);
            float2 v0, v1;
            v0.x = fmaf(-2.0f, acc[i][j][0], x0 + cA);
            v0.y = fmaf(-2.0f, acc[i][j][1], x0 + cB);
            v1.x = fmaf(-2.0f, acc[i][j][2], x1 + cA);
            v1.y = fmaf(-2.0f, acc[i][j][3], x1 + cB);
            *reinterpret_cast<float2*>(&out[(size_t)r0 * C_ROWS + col]) = v0;
            *reinterpret_cast<float2*>(&out[(size_t)r1 * C_ROWS + col]) = v1;
        }
    }
}

// ---------------- host launch ----------------
extern "C" void kernel_launch(void* const* d_in, const int* in_sizes, int n_in,
                              void* d_out, int out_size) {
    (void)in_sizes; (void)n_in; (void)out_size;
    const float* feat = (const float*)d_in[0];
    const float* cent = (const float*)d_in[1];
    float* out = (float*)d_out;

    void *p_fb = nullptr, *p_cb = nullptr, *p_x2 = nullptr, *p_c2 = nullptr;
    cudaGetSymbolAddress(&p_fb, g_featb);
    cudaGetSymbolAddress(&p_cb, g_centb);
    cudaGetSymbolAddress(&p_x2, g_x2);
    cudaGetSymbolAddress(&p_c2, g_c2);

    prep_kernel<<<B_ROWS + C_ROWS, 256>>>(feat, cent);

    cudaFuncSetAttribute(dist_gemm_kernel,
                         cudaFuncAttributeMaxDynamicSharedMemorySize, SMEM_BYTES);

    int grid = (B_ROWS / BM) * (C_ROWS / BN);   // 4096
    dist_gemm_kernel<<<grid, 256, SMEM_BYTES>>>(
        (const __nv_bfloat16*)p_fb, (const __nv_bfloat16*)p_cb,
        (const float*)p_x2, (const float*)p_c2, out);
}

// round 7
// speedup vs baseline: 4.1523x; 1.0804x over previous
#include <cuda_runtime.h>
#include <cuda_bf16.h>
#include <cstdint>

// ---------------- problem shape ----------------
static constexpr int B_ROWS = 16384;
static constexpr int C_ROWS = 4096;
static constexpr int KDIM   = 1024;

// ---------------- GEMM tiling (bf16) ----------------
static constexpr int BM = 128;
static constexpr int BN = 128;
static constexpr int BK = 64;                 // bf16 elems per K-chunk
static constexpr int STAGES = 3;              // 110.6KB -> 2 CTAs/SM
static constexpr int KTILES = KDIM / BK;      // 16
static constexpr int KSTEPS = BK / 16;        // 4 mma k-steps per chunk

// padded smem rows: 64 + 8 halves -> 144B stride (conflict-free ldmatrix)
static constexpr int ROW_H   = BK + 8;        // 72 halves
static constexpr int ROWB    = ROW_H * 2;     // 144 bytes
static constexpr int TILE_B  = 128 * ROWB;    // 18432 bytes per (A or B) stage
static constexpr int OFF_B0  = STAGES * TILE_B;
static constexpr int SMEM_BYTES = 2 * STAGES * TILE_B;  // 110592

// ---------------- device scratch (no cudaMalloc allowed) ----------------
__device__ __nv_bfloat16 g_featb[(size_t)B_ROWS * KDIM];
__device__ __nv_bfloat16 g_centb[(size_t)C_ROWS * KDIM];
__device__ float g_x2[B_ROWS];
__device__ float g_c2[C_ROWS];

// ---------------- PTX helpers ----------------
__device__ __forceinline__ uint32_t smem_u32(const void* p) {
    uint32_t a;
    asm("{ .reg .u64 t; cvta.to.shared.u64 t, %1; cvt.u32.u64 %0, t; }"
        : "=r"(a) : "l"(p));
    return a;
}

__device__ __forceinline__ void cp_async16(uint32_t s_addr, const void* g_addr) {
    asm volatile("cp.async.cg.shared.global [%0], [%1], 16;"
                 :: "r"(s_addr), "l"(g_addr) : "memory");
}
__device__ __forceinline__ void cp_commit() {
    asm volatile("cp.async.commit_group;" ::: "memory");
}
template <int N>
__device__ __forceinline__ void cp_wait() {
    asm volatile("cp.async.wait_group %0;" :: "n"(N) : "memory");
}

__device__ __forceinline__ void ldsm_x4(uint32_t& r0, uint32_t& r1, uint32_t& r2, uint32_t& r3,
                                        uint32_t addr) {
    asm volatile("ldmatrix.sync.aligned.m8n8.x4.shared.b16 {%0,%1,%2,%3}, [%4];"
                 : "=r"(r0), "=r"(r1), "=r"(r2), "=r"(r3) : "r"(addr));
}

__device__ __forceinline__ void mma16816(float* d, uint32_t a0, uint32_t a1, uint32_t a2,
                                         uint32_t a3, uint32_t b0, uint32_t b1) {
    asm volatile(
        "mma.sync.aligned.m16n8k16.row.col.f32.bf16.bf16.f32 "
        "{%0,%1,%2,%3}, {%4,%5,%6,%7}, {%8,%9}, {%0,%1,%2,%3};"
        : "+f"(d[0]), "+f"(d[1]), "+f"(d[2]), "+f"(d[3])
        : "r"(a0), "r"(a1), "r"(a2), "r"(a3), "r"(b0), "r"(b1));
}

// ---------------- fused prep: fp32 -> bf16 + row sum-of-squares (feat AND cent) ----------------
__global__ __launch_bounds__(256)
void prep_kernel(const float* __restrict__ feat, const float* __restrict__ cent) {
    int blk = blockIdx.x;
    const float* in;
    __nv_bfloat16* outbf;
    float* sq;
    int row;
    if (blk < B_ROWS) {
        row = blk; in = feat; outbf = g_featb; sq = g_x2;
    } else {
        row = blk - B_ROWS; in = cent; outbf = g_centb; sq = g_c2;
    }
    int t = threadIdx.x;
    float4 v = reinterpret_cast<const float4*>(in)[(size_t)row * 256 + t];

    float s = fmaf(v.x, v.x, fmaf(v.y, v.y, fmaf(v.z, v.z, v.w * v.w)));
    #pragma unroll
    for (int o = 16; o > 0; o >>= 1) s += __shfl_xor_sync(0xFFFFFFFFu, s, o);
    __shared__ float ws[8];
    if ((t & 31) == 0) ws[t >> 5] = s;
    __syncthreads();
    if (t < 8) {
        float x = ws[t];
        #pragma unroll
        for (int o = 4; o > 0; o >>= 1) x += __shfl_xor_sync(0xFFu, x, o);
        if (t == 0) sq[row] = x;
    }

    union { __nv_bfloat162 h2[2]; uint2 u; } pk;
    pk.h2[0] = __floats2bfloat162_rn(v.x, v.y);
    pk.h2[1] = __floats2bfloat162_rn(v.z, v.w);
    reinterpret_cast<uint2*>(outbf)[(size_t)row * 256 + t] = pk.u;
}

// ---------------- main bf16 GEMM + fused distance epilogue ----------------
// 2 CTAs/SM. Software-pipelined fragments: A quads ping-pong (prefetch mtile
// i+1 during mtile i's MMAs); next k-step's B frags + A0 issued right after
// the last MMA reading the current bf (WAR handled by scoreboard). cp.async
// stage loads split A-half / B-half across k-steps 0/1 to de-burst the
// crossbar after the barrier.
__global__ __launch_bounds__(256, 2)
void dist_gemm_kernel(const __nv_bfloat16* __restrict__ Abf,
                      const __nv_bfloat16* __restrict__ Bbf,
                      const float* __restrict__ x2,
                      const float* __restrict__ c2,
                      float* __restrict__ out) {
    extern __shared__ char smem[];
    const uint32_t sb = smem_u32(smem);
    const int tid = threadIdx.x;
    const int wid = tid >> 5;
    const int lane = tid & 31;

    const int nt = blockIdx.x & 31;           // 32 n-tiles (n-fast for L2 reuse)
    const int mt = blockIdx.x >> 5;           // 128 m-tiles
    const int m_base = mt * BM;
    const int n_base = nt * BN;

    // cp.async mapping: 4 x 16B chunks per thread per (A or B) stage
    const int ld_row = tid >> 3;
    const int ld_c16 = (tid & 7) * 16;
    const __nv_bfloat16* gA = Abf + (size_t)(m_base + ld_row) * KDIM + (tid & 7) * 8;
    const __nv_bfloat16* gB = Bbf + (size_t)(n_base + ld_row) * KDIM + (tid & 7) * 8;
    const uint32_t sA0 = sb + ld_row * ROWB + ld_c16;
    const uint32_t sB0 = sb + OFF_B0 + ld_row * ROWB + ld_c16;

    auto load_A = [&](int s, int kt) {
        const uint32_t st = sA0 + s * TILE_B;
        const size_t gk = (size_t)kt * BK;
        #pragma unroll
        for (int i = 0; i < 4; i++)
            cp_async16(st + i * 32 * ROWB, gA + gk + (size_t)i * 32 * KDIM);
    };
    auto load_B = [&](int s, int kt) {
        const uint32_t st = sB0 + s * TILE_B;
        const size_t gk = (size_t)kt * BK;
        #pragma unroll
        for (int i = 0; i < 4; i++)
            cp_async16(st + i * 32 * ROWB, gB + gk + (size_t)i * 32 * KDIM);
    };

    // warp tiling: 2 (M) x 4 (N); each warp 64x32
    const int wm = wid >> 2;
    const int wn = wid & 3;

    float acc[4][4][4];
    #pragma unroll
    for (int i = 0; i < 4; i++)
        #pragma unroll
        for (int j = 0; j < 4; j++)
            #pragma unroll
            for (int f = 0; f < 4; f++) acc[i][j][f] = 0.0f;

    const uint32_t a_addr0 = (uint32_t)((wm * 64 + (lane & 15)) * ROWB + (lane >> 4) * 16);
    const uint32_t b_addr0 = (uint32_t)((wn * 32 + (lane >> 4) * 8 + (lane & 7)) * ROWB
                                        + ((lane >> 3) & 1) * 16);

    // prologue: fill 2 of 3 stages
    load_A(0, 0); load_B(0, 0); cp_commit();
    load_A(1, 1); load_B(1, 1); cp_commit();

    #pragma unroll 1
    for (int kt = 0; kt < KTILES; kt++) {
        const int s = kt % STAGES;
        cp_wait<1>();
        __syncthreads();        // stage kt visible; stage (kt+2)%3 drained at kt-1

        const uint32_t sAs = sb + s * TILE_B;
        const uint32_t sBs = sb + OFF_B0 + s * TILE_B;
        const uint32_t aA = sAs + a_addr0;
        const uint32_t aB = sBs + b_addr0;

        const int s_next = (kt + 2) % STAGES;
        const bool more = (kt + 2 < KTILES);

        // cold-start frags for k-step 0
        uint32_t bf[4][2];
        uint32_t ac[4], an[4];
        ldsm_x4(bf[0][0], bf[0][1], bf[1][0], bf[1][1], aB);
        ldsm_x4(bf[2][0], bf[2][1], bf[3][0], bf[3][1], aB + 16 * ROWB);
        ldsm_x4(ac[0], ac[1], ac[2], ac[3], aA);

        #pragma unroll
        for (int kk = 0; kk < KSTEPS; kk++) {
            const uint32_t k0b = kk * 32;
            // mtile 0 (prefetch A1)
            ldsm_x4(an[0], an[1], an[2], an[3], aA + 1 * 16 * ROWB + k0b);
            #pragma unroll
            for (int j = 0; j < 4; j++)
                mma16816(acc[0][j], ac[0], ac[1], ac[2], ac[3], bf[j][0], bf[j][1]);
            // mtile 1 (prefetch A2)
            ldsm_x4(ac[0], ac[1], ac[2], ac[3], aA + 2 * 16 * ROWB + k0b);
            #pragma unroll
            for (int j = 0; j < 4; j++)
                mma16816(acc[1][j], an[0], an[1], an[2], an[3], bf[j][0], bf[j][1]);
            // mtile 2 (prefetch A3)
            ldsm_x4(an[0], an[1], an[2], an[3], aA + 3 * 16 * ROWB + k0b);
            #pragma unroll
            for (int j = 0; j < 4; j++)
                mma16816(acc[2][j], ac[0], ac[1], ac[2], ac[3], bf[j][0], bf[j][1]);
            // mtile 3
            #pragma unroll
            for (int j = 0; j < 4; j++)
                mma16816(acc[3][j], an[0], an[1], an[2], an[3], bf[j][0], bf[j][1]);
            // preload next k-step's B + A0 (WAR on bf/ac is issue-ordered, safe)
            if (kk < KSTEPS - 1) {
                const uint32_t k1b = k0b + 32;
                ldsm_x4(bf[0][0], bf[0][1], bf[1][0], bf[1][1], aB + k1b);
                ldsm_x4(bf[2][0], bf[2][1], bf[3][0], bf[3][1], aB + 16 * ROWB + k1b);
                ldsm_x4(ac[0], ac[1], ac[2], ac[3], aA + k1b);
            }
            // spread the next-stage cp.async across k-steps 0 and 1
            if (kk == 0 && more) load_A(s_next, kt + 2);
            if (kk == 1) { if (more) load_B(s_next, kt + 2); cp_commit(); }
        }
    }

    // ---------------- epilogue: dist = x2[m] + c2[n] - 2*acc ----------------
    const int g = lane >> 2;
    const int q = lane & 3;
    #pragma unroll
    for (int i = 0; i < 4; i++) {
        const int r0 = m_base + wm * 64 + i * 16 + g;
        const int r1 = r0 + 8;
        const float x0 = __ldg(&x2[r0]);
        const float x1 = __ldg(&x2[r1]);
        #pragma unroll
        for (int j = 0; j < 4; j++) {
            const int col = n_base + wn * 32 + j * 8 + q * 2;
            const float cA = __ldg(&c2[col]);
            const float cB = __ldg(&c2[col + 1]);
            float2 v0, v1;
            v0.x = fmaf(-2.0f, acc[i][j][0], x0 + cA);
            v0.y = fmaf(-2.0f, acc[i][j][1], x0 + cB);
            v1.x = fmaf(-2.0f, acc[i][j][2], x1 + cA);
            v1.y = fmaf(-2.0f, acc[i][j][3], x1 + cB);
            *reinterpret_cast<float2*>(&out[(size_t)r0 * C_ROWS + col]) = v0;
            *reinterpret_cast<float2*>(&out[(size_t)r1 * C_ROWS + col]) = v1;
        }
    }
}

// ---------------- host launch ----------------
extern "C" void kernel_launch(void* const* d_in, const int* in_sizes, int n_in,
                              void* d_out, int out_size) {
    (void)in_sizes; (void)n_in; (void)out_size;
    const float* feat = (const float*)d_in[0];
    const float* cent = (const float*)d_in[1];
    float* out = (float*)d_out;

    void *p_fb = nullptr, *p_cb = nullptr, *p_x2 = nullptr, *p_c2 = nullptr;
    cudaGetSymbolAddress(&p_fb, g_featb);
    cudaGetSymbolAddress(&p_cb, g_centb);
    cudaGetSymbolAddress(&p_x2, g_x2);
    cudaGetSymbolAddress(&p_c2, g_c2);

    prep_kernel<<<B_ROWS + C_ROWS, 256>>>(feat, cent);

    cudaFuncSetAttribute(dist_gemm_kernel,
                         cudaFuncAttributeMaxDynamicSharedMemorySize, SMEM_BYTES);

    int grid = (B_ROWS / BM) * (C_ROWS / BN);   // 4096
    dist_gemm_kernel<<<grid, 256, SMEM_BYTES>>>(
        (const __nv_bfloat16*)p_fb, (const __nv_bfloat16*)p_cb,
        (const float*)p_x2, (const float*)p_c2, out);
}

// round 9
// speedup vs baseline: 4.7915x; 1.1539x over previous
#include <cuda_runtime.h>
#include <cuda_bf16.h>
#include <cstdint>

// ---------------- problem shape ----------------
static constexpr int B_ROWS = 16384;
static constexpr int C_ROWS = 4096;
static constexpr int KDIM   = 1024;

// ---------------- GEMM tiling (bf16) ----------------
static constexpr int BM = 128;
static constexpr int BN = 128;
static constexpr int BK = 64;                 // bf16 elems per K-chunk
static constexpr int STAGES = 3;
static constexpr int KTILES = KDIM / BK;      // 16
static constexpr int KSTEPS = BK / 16;        // 4 mma k-steps per chunk

// padded smem rows: 64 + 8 halves -> 144B stride (conflict-free ldmatrix)
static constexpr int ROW_H   = BK + 8;        // 72 halves
static constexpr int ROWB    = ROW_H * 2;     // 144 bytes
static constexpr int TILE_B  = 128 * ROWB;    // 18432 bytes per (A or B) stage
static constexpr int OFF_TILES = 128;         // mbarriers live below
static constexpr int OFF_B0  = STAGES * TILE_B;
static constexpr int SMEM_BYTES = OFF_TILES + 2 * STAGES * TILE_B;  // 110720

// ---------------- device scratch (no cudaMalloc allowed) ----------------
__device__ __nv_bfloat16 g_featb[(size_t)B_ROWS * KDIM];
__device__ __nv_bfloat16 g_centb[(size_t)C_ROWS * KDIM];
__device__ float g_x2[B_ROWS];
__device__ float g_c2[C_ROWS];

// ---------------- PTX helpers ----------------
__device__ __forceinline__ uint32_t smem_u32(const void* p) {
    uint32_t a;
    asm("{ .reg .u64 t; cvta.to.shared.u64 t, %1; cvt.u32.u64 %0, t; }"
        : "=r"(a) : "l"(p));
    return a;
}

__device__ __forceinline__ void cp_async16(uint32_t s_addr, const void* g_addr) {
    asm volatile("cp.async.cg.shared.global [%0], [%1], 16;"
                 :: "r"(s_addr), "l"(g_addr) : "memory");
}

#define MBARRIER_INIT(addr, count) \
    asm volatile("mbarrier.init.shared.b64 [%0], %1;" :: "r"((uint32_t)(addr)), "r"((uint32_t)(count)) : "memory")

#define MBARRIER_ARRIVE(addr) \
    asm volatile("mbarrier.arrive.shared.b64 _, [%0];" :: "r"((uint32_t)(addr)) : "memory")

// Deferred arrive when this thread's prior cp.asyncs complete. MUST be .noinc:
// the default variant bumps the pending count by 1 at execution and removes it
// at completion (net zero vs the init count) -> the phase never completes
// (round-8 hang). .noinc makes the completion count against the init count.
#define CP_MBAR_ARRIVE_NOINC(addr) \
    asm volatile("cp.async.mbarrier.arrive.noinc.shared.b64 [%0];" :: "r"((uint32_t)(addr)) : "memory")

#define MBARRIER_WAIT_PARITY(addr, parity) do {                                   \
    uint32_t _mbar = (uint32_t)(addr);                                            \
    uint32_t _par  = (uint32_t)(parity);                                          \
    uint32_t _done;                                                               \
    asm volatile("{\n\t.reg .pred p;\n\t"                                         \
        "mbarrier.try_wait.parity.acquire.cta.shared::cta.b64 p, [%1], %2;\n\t"   \
        "selp.b32 %0, 1, 0, p;\n\t}"                                              \
        : "=r"(_done) : "r"(_mbar), "r"(_par) : "memory");                        \
    if (!_done) {                                                                 \
        asm volatile("{\n\t.reg .pred P1;\n\t"                                    \
            "WAIT_LOOP_%=:\n\t"                                                   \
            "mbarrier.try_wait.parity.acquire.cta.shared::cta.b64 P1, [%0], %1, 0x989680;\n\t" \
            "@P1 bra.uni WAIT_DONE_%=;\n\t"                                       \
            "bra.uni WAIT_LOOP_%=;\n\t"                                           \
            "WAIT_DONE_%=:\n\t}"                                                  \
            :: "r"(_mbar), "r"(_par) : "memory");                                 \
    }                                                                             \
} while (0)

__device__ __forceinline__ void ldsm_x4(uint32_t& r0, uint32_t& r1, uint32_t& r2, uint32_t& r3,
                                        uint32_t addr) {
    asm volatile("ldmatrix.sync.aligned.m8n8.x4.shared.b16 {%0,%1,%2,%3}, [%4];"
                 : "=r"(r0), "=r"(r1), "=r"(r2), "=r"(r3) : "r"(addr));
}

__device__ __forceinline__ void mma16816(float* d, uint32_t a0, uint32_t a1, uint32_t a2,
                                         uint32_t a3, uint32_t b0, uint32_t b1) {
    asm volatile(
        "mma.sync.aligned.m16n8k16.row.col.f32.bf16.bf16.f32 "
        "{%0,%1,%2,%3}, {%4,%5,%6,%7}, {%8,%9}, {%0,%1,%2,%3};"
        : "+f"(d[0]), "+f"(d[1]), "+f"(d[2]), "+f"(d[3])
        : "r"(a0), "r"(a1), "r"(a2), "r"(a3), "r"(b0), "r"(b1));
}

// ---------------- prep: fp32 -> bf16 + row sum-of-squares, 2 rows/block (MLP=2) ----------------
__global__ __launch_bounds__(256)
void prep_kernel(const float* __restrict__ feat, const float* __restrict__ cent) {
    const int t = threadIdx.x;
    const int r0g = blockIdx.x * 2;
    const int r1g = r0g + 1;

    const float* in0; __nv_bfloat16* o0; float* q0; int r0;
    if (r0g < B_ROWS) { r0 = r0g; in0 = feat; o0 = g_featb; q0 = g_x2; }
    else              { r0 = r0g - B_ROWS; in0 = cent; o0 = g_centb; q0 = g_c2; }
    const float* in1; __nv_bfloat16* o1; float* q1; int r1;
    if (r1g < B_ROWS) { r1 = r1g; in1 = feat; o1 = g_featb; q1 = g_x2; }
    else              { r1 = r1g - B_ROWS; in1 = cent; o1 = g_centb; q1 = g_c2; }

    float4 v0 = reinterpret_cast<const float4*>(in0)[(size_t)r0 * 256 + t];
    float4 v1 = reinterpret_cast<const float4*>(in1)[(size_t)r1 * 256 + t];

    float s0 = fmaf(v0.x, v0.x, fmaf(v0.y, v0.y, fmaf(v0.z, v0.z, v0.w * v0.w)));
    float s1 = fmaf(v1.x, v1.x, fmaf(v1.y, v1.y, fmaf(v1.z, v1.z, v1.w * v1.w)));
    #pragma unroll
    for (int o = 16; o > 0; o >>= 1) {
        s0 += __shfl_xor_sync(0xFFFFFFFFu, s0, o);
        s1 += __shfl_xor_sync(0xFFFFFFFFu, s1, o);
    }
    __shared__ float ws0[8], ws1[8];
    if ((t & 31) == 0) { ws0[t >> 5] = s0; ws1[t >> 5] = s1; }
    __syncthreads();
    if (t == 0) {
        float x = 0.0f;
        #pragma unroll
        for (int i = 0; i < 8; i++) x += ws0[i];
        q0[r0] = x;
    }
    if (t == 1) {
        float x = 0.0f;
        #pragma unroll
        for (int i = 0; i < 8; i++) x += ws1[i];
        q1[r1] = x;
    }

    union { __nv_bfloat162 h2[2]; uint2 u; } p0, p1;
    p0.h2[0] = __floats2bfloat162_rn(v0.x, v0.y);
    p0.h2[1] = __floats2bfloat162_rn(v0.z, v0.w);
    p1.h2[0] = __floats2bfloat162_rn(v1.x, v1.y);
    p1.h2[1] = __floats2bfloat162_rn(v1.z, v1.w);
    reinterpret_cast<uint2*>(o0)[(size_t)r0 * 256 + t] = p0.u;
    reinterpret_cast<uint2*>(o1)[(size_t)r1 * 256 + t] = p1.u;
}

// ---------------- main bf16 GEMM + fused distance epilogue ----------------
// Convoy-free pipeline: per-stage full/empty mbarriers instead of
// __syncthreads. full[s] (count 256) completes via per-thread
// cp.async.mbarrier.arrive.noinc; warps consume independently via try_wait;
// empty[s] (count 8, lane0/warp) re-arms a stage once all warps consumed it.
__global__ __launch_bounds__(256, 2)
void dist_gemm_kernel(const __nv_bfloat16* __restrict__ Abf,
                      const __nv_bfloat16* __restrict__ Bbf,
                      const float* __restrict__ x2,
                      const float* __restrict__ c2,
                      float* __restrict__ out) {
    extern __shared__ char smem[];
    const uint32_t sb = smem_u32(smem);
    const int tid = threadIdx.x;
    const int wid = tid >> 5;
    const int lane = tid & 31;

    const int nt = blockIdx.x & 31;           // 32 n-tiles (n-fast for L2 reuse)
    const int mt = blockIdx.x >> 5;           // 128 m-tiles
    const int m_base = mt * BM;
    const int n_base = nt * BN;

    // mbarriers: full[s] at sb+8s, empty[s] at sb+24+8s
    const uint32_t mb_full0 = sb;
    const uint32_t mb_empty0 = sb + 24;
    if (tid == 0) {
        #pragma unroll
        for (int s = 0; s < STAGES; s++) {
            MBARRIER_INIT(mb_full0 + 8 * s, 256);
            MBARRIER_INIT(mb_empty0 + 8 * s, 8);
        }
    }
    __syncthreads();

    const uint32_t tb = sb + OFF_TILES;

    // cp.async mapping: 4 x 16B chunks per thread per (A or B) stage
    const int ld_row = tid >> 3;
    const int ld_c16 = (tid & 7) * 16;
    const __nv_bfloat16* gA = Abf + (size_t)(m_base + ld_row) * KDIM + (tid & 7) * 8;
    const __nv_bfloat16* gB = Bbf + (size_t)(n_base + ld_row) * KDIM + (tid & 7) * 8;
    const uint32_t sA0 = tb + ld_row * ROWB + ld_c16;
    const uint32_t sB0 = tb + OFF_B0 + ld_row * ROWB + ld_c16;

    auto load_A = [&](int s, int kt) {
        const uint32_t st = sA0 + s * TILE_B;
        const size_t gk = (size_t)kt * BK;
        #pragma unroll
        for (int i = 0; i < 4; i++)
            cp_async16(st + i * 32 * ROWB, gA + gk + (size_t)i * 32 * KDIM);
    };
    auto load_B = [&](int s, int kt) {
        const uint32_t st = sB0 + s * TILE_B;
        const size_t gk = (size_t)kt * BK;
        #pragma unroll
        for (int i = 0; i < 4; i++)
            cp_async16(st + i * 32 * ROWB, gB + gk + (size_t)i * 32 * KDIM);
    };

    // warp tiling: 2 (M) x 4 (N); each warp 64x32
    const int wm = wid >> 2;
    const int wn = wid & 3;

    float acc[4][4][4];
    #pragma unroll
    for (int i = 0; i < 4; i++)
        #pragma unroll
        for (int j = 0; j < 4; j++)
            #pragma unroll
            for (int f = 0; f < 4; f++) acc[i][j][f] = 0.0f;

    const uint32_t a_addr0 = (uint32_t)((wm * 64 + (lane & 15)) * ROWB + (lane >> 4) * 16);
    const uint32_t b_addr0 = (uint32_t)((wn * 32 + (lane >> 4) * 8 + (lane & 7)) * ROWB
                                        + ((lane >> 3) & 1) * 16);

    // prologue: writes w=0,1 (producer parity 1 -> immediate pass on fresh mbar)
    MBARRIER_WAIT_PARITY(mb_empty0 + 0, 1);
    load_A(0, 0); load_B(0, 0); CP_MBAR_ARRIVE_NOINC(mb_full0 + 0);
    MBARRIER_WAIT_PARITY(mb_empty0 + 8, 1);
    load_A(1, 1); load_B(1, 1); CP_MBAR_ARRIVE_NOINC(mb_full0 + 8);

    #pragma unroll 1
    for (int kt = 0; kt < KTILES; kt++) {
        const int s = kt % STAGES;
        const int ph = (kt / 3) & 1;
        MBARRIER_WAIT_PARITY(mb_full0 + 8 * s, ph);   // per-warp, no convoy

        const uint32_t aA = tb + s * TILE_B + a_addr0;
        const uint32_t aB = tb + OFF_B0 + s * TILE_B + b_addr0;

        const int w = kt + 2;                          // stage-write index
        const int s2 = w % STAGES;
        const int pph = 1 ^ ((w / 3) & 1);             // producer parity for w
        const bool more = (w < KTILES);

        // cold-start frags for k-step 0
        uint32_t bf[4][2];
        uint32_t ac[4], an[4];
        ldsm_x4(bf[0][0], bf[0][1], bf[1][0], bf[1][1], aB);
        ldsm_x4(bf[2][0], bf[2][1], bf[3][0], bf[3][1], aB + 16 * ROWB);
        ldsm_x4(ac[0], ac[1], ac[2], ac[3], aA);

        #pragma unroll
        for (int kk = 0; kk < KSTEPS; kk++) {
            const uint32_t k0b = kk * 32;
            // mtile 0 (prefetch A1)
            ldsm_x4(an[0], an[1], an[2], an[3], aA + 1 * 16 * ROWB + k0b);
            #pragma unroll
            for (int j = 0; j < 4; j++)
                mma16816(acc[0][j], ac[0], ac[1], ac[2], ac[3], bf[j][0], bf[j][1]);
            // mtile 1 (prefetch A2)
            ldsm_x4(ac[0], ac[1], ac[2], ac[3], aA + 2 * 16 * ROWB + k0b);
            #pragma unroll
            for (int j = 0; j < 4; j++)
                mma16816(acc[1][j], an[0], an[1], an[2], an[3], bf[j][0], bf[j][1]);
            // mtile 2 (prefetch A3)
            ldsm_x4(an[0], an[1], an[2], an[3], aA + 3 * 16 * ROWB + k0b);
            #pragma unroll
            for (int j = 0; j < 4; j++)
                mma16816(acc[2][j], ac[0], ac[1], ac[2], ac[3], bf[j][0], bf[j][1]);
            // mtile 3
            #pragma unroll
            for (int j = 0; j < 4; j++)
                mma16816(acc[3][j], an[0], an[1], an[2], an[3], bf[j][0], bf[j][1]);
            // preload next k-step's B + A0 (WAR on bf/ac is issue-ordered, safe)
            if (kk < KSTEPS - 1) {
                const uint32_t k1b = k0b + 32;
                ldsm_x4(bf[0][0], bf[0][1], bf[1][0], bf[1][1], aB + k1b);
                ldsm_x4(bf[2][0], bf[2][1], bf[3][0], bf[3][1], aB + 16 * ROWB + k1b);
                ldsm_x4(ac[0], ac[1], ac[2], ac[3], aA + k1b);
            }
            // producer side, spread across k-steps 0/1
            if (kk == 0 && more) {
                MBARRIER_WAIT_PARITY(mb_empty0 + 8 * s2, pph);
                load_A(s2, w);
            }
            if (kk == 1 && more) {
                load_B(s2, w);
                CP_MBAR_ARRIVE_NOINC(mb_full0 + 8 * s2);
            }
        }

        // consumer done with stage s (frags in regs once MMAs issued)
        if (lane == 0) MBARRIER_ARRIVE(mb_empty0 + 8 * s);
    }

    // ---------------- epilogue: dist = x2[m] + c2[n] - 2*acc ----------------
    const int g = lane >> 2;
    const int q = lane & 3;
    #pragma unroll
    for (int i = 0; i < 4; i++) {
        const int r0 = m_base + wm * 64 + i * 16 + g;
        const int r1 = r0 + 8;
        const float x0 = __ldg(&x2[r0]);
        const float x1 = __ldg(&x2[r1]);
        #pragma unroll
        for (int j = 0; j < 4; j++) {
            const int col = n_base + wn * 32 + j * 8 + q * 2;
            const float cA = __ldg(&c2[col]);
            const float cB = __ldg(&c2[col + 1]);
            float2 v0, v1;
            v0.x = fmaf(-2.0f, acc[i][j][0], x0 + cA);
            v0.y = fmaf(-2.0f, acc[i][j][1], x0 + cB);
            v1.x = fmaf(-2.0f, acc[i][j][2], x1 + cA);
            v1.y = fmaf(-2.0f, acc[i][j][3], x1 + cB);
            *reinterpret_cast<float2*>(&out[(size_t)r0 * C_ROWS + col]) = v0;
            *reinterpret_cast<float2*>(&out[(size_t)r1 * C_ROWS + col]) = v1;
        }
    }
}

// ---------------- host launch ----------------
extern "C" void kernel_launch(void* const* d_in, const int* in_sizes, int n_in,
                              void* d_out, int out_size) {
    (void)in_sizes; (void)n_in; (void)out_size;
    const float* feat = (const float*)d_in[0];
    const float* cent = (const float*)d_in[1];
    float* out = (float*)d_out;

    void *p_fb = nullptr, *p_cb = nullptr, *p_x2 = nullptr, *p_c2 = nullptr;
    cudaGetSymbolAddress(&p_fb, g_featb);
    cudaGetSymbolAddress(&p_cb, g_centb);
    cudaGetSymbolAddress(&p_x2, g_x2);
    cudaGetSymbolAddress(&p_c2, g_c2);

    prep_kernel<<<(B_ROWS + C_ROWS) / 2, 256>>>(feat, cent);

    cudaFuncSetAttribute(dist_gemm_kernel,
                         cudaFuncAttributeMaxDynamicSharedMemorySize, SMEM_BYTES);

    int grid = (B_ROWS / BM) * (C_ROWS / BN);   // 4096
    dist_gemm_kernel<<<grid, 256, SMEM_BYTES>>>(
        (const __nv_bfloat16*)p_fb, (const __nv_bfloat16*)p_cb,
        (const float*)p_x2, (const float*)p_c2, out);
}